// round 14
// baseline (speedup 1.0000x reference)
#include <cuda_runtime.h>
#include <cuda_fp16.h>
#include <math.h>
#include <cstdint>

#define BB  64
#define NN  100
#define MM  99
#define NIN 32
#define NG  32
#define NF  64
#define NROWS (BB * NN * MM)             // 633600 — globally contiguous GEMM rows

static __device__ __forceinline__ float tanh_fast(float x) {
    float y; asm("tanh.approx.f32 %0, %1;" : "=f"(y) : "f"(x)); return y;
}
static __device__ __forceinline__ uint32_t packh2(float a, float b) {
    __half2 h = __floats2half2_rn(a, b);
    return *reinterpret_cast<uint32_t*>(&h);
}
static __device__ __forceinline__ float2 unpackh2(uint32_t u) {
    __half2 h = *reinterpret_cast<__half2*>(&u);
    return __half22float2(h);
}

#define MMA_F16(c, a, b0, b1v)                                                     \
    asm volatile("mma.sync.aligned.m16n8k16.row.col.f32.f16.f16.f32 "              \
        "{%0,%1,%2,%3},{%4,%5,%6,%7},{%8,%9},{%0,%1,%2,%3};"                       \
        : "+f"((c)[0]), "+f"((c)[1]), "+f"((c)[2]), "+f"((c)[3])                   \
        : "r"((a)[0]), "r"((a)[1]), "r"((a)[2]), "r"((a)[3]), "r"(b0), "r"(b1v))

__device__ float    g_x[BB * NN * NF];       // x = features @ W0 (f32)
__device__ uint4    g_w1h[2 * 4 * 32];       // W1 fp16 fragment-major
__device__ uint4    g_w2h[4 * 4 * 32];       // W2 fp16 fragment-major
__device__ uint32_t g_f[(size_t)NROWS * 32]; // F filter values, fp16 (81 MB, L2-resident)

// ---------------------------------------------------------------------------
// Fused setup: fp16 fragment weight prep + x = features @ W0
// ---------------------------------------------------------------------------
#define W1H_N   256
#define W2H_N   512
#define SETUP_W (W1H_N + W2H_N)           // 768
__global__ void setup_kernel(const float* __restrict__ W1,
                             const float* __restrict__ W2,
                             const float* __restrict__ features,
                             const float* __restrict__ W0)
{
    int idx = blockIdx.x * blockDim.x + threadIdx.x;
    if (idx < SETUP_W) {
        const float* W = (idx < W1H_N) ? W1 : W2;
        int e = (idx < W1H_N) ? idx : idx - W1H_N;
        int lane = e & 31, blk = e >> 5;
        int ks = blk >> 2, ntp = blk & 3;
        int g = lane >> 2, t = lane & 3;
        int kb = ks * 16;
        int n0 = (2 * ntp) * 8 + g;
        int n1 = (2 * ntp + 1) * 8 + g;
        uint4 v;
        v.x = packh2(W[(kb + 2 * t) * NF + n0],     W[(kb + 2 * t + 1) * NF + n0]);
        v.y = packh2(W[(kb + 2 * t + 8) * NF + n0], W[(kb + 2 * t + 9) * NF + n0]);
        v.z = packh2(W[(kb + 2 * t) * NF + n1],     W[(kb + 2 * t + 1) * NF + n1]);
        v.w = packh2(W[(kb + 2 * t + 8) * NF + n1], W[(kb + 2 * t + 9) * NF + n1]);
        if (idx < W1H_N) g_w1h[e] = v; else g_w2h[e] = v;
        return;
    }
    int ix = idx - SETUP_W;
    if (ix >= BB * NN * NF) return;
    int f   = ix & (NF - 1);
    int row = ix >> 6;
    const float* feat = features + row * NIN;
    float acc = 0.f;
#pragma unroll
    for (int k = 0; k < NIN; k++)
        acc = fmaf(feat[k], W0[k * NF + f], acc);
    g_x[ix] = acc;
}

// ---------------------------------------------------------------------------
// Kernel A: dense filter GEMM over all 633600 rows.
// F = tanh(rbf @ W1 + b1) @ W2 + b2, stored fp16.
// 256 threads = 8 independent warps x 16 rows. A-fragments straight from
// global; tanh feeds GEMM2 A-registers directly; F written via STG.32.
// ---------------------------------------------------------------------------
__global__ __launch_bounds__(256)
void gemm_kernel(const float* __restrict__ rbf,
                 const float* __restrict__ b1,
                 const float* __restrict__ b2)
{
    __shared__ uint4 sB1h[W1H_N];
    __shared__ uint4 sB2h[W2H_N];
    __shared__ float sBV[NF];
    __shared__ float sB2V[NF];

    const int tid  = threadIdx.x;
    const int wid  = tid >> 5;
    const int lane = tid & 31;
    const int g    = lane >> 2;
    const int t    = lane & 3;

    for (int idx = tid; idx < W1H_N; idx += 256) sB1h[idx] = g_w1h[idx];
    for (int idx = tid; idx < W2H_N; idx += 256) sB2h[idx] = g_w2h[idx];
    if (tid < NF) { sBV[tid] = b1[tid]; sB2V[tid] = b2[tid]; }
    __syncthreads();

    const int rowbase = blockIdx.x * 128 + wid * 16;      // 4950 CTAs cover exactly
    const float* rp0 = rbf + (size_t)(rowbase + g) * NG;
    const float* rp1 = rbf + (size_t)(rowbase + g + 8) * NG;

    // ---- A fragments for GEMM1 straight from global ----
    uint32_t af[2][4];
#pragma unroll
    for (int ks = 0; ks < 2; ks++) {
        float2 v00 = *(const float2*)(rp0 + 16 * ks + 2 * t);
        float2 v01 = *(const float2*)(rp0 + 16 * ks + 2 * t + 8);
        float2 v10 = *(const float2*)(rp1 + 16 * ks + 2 * t);
        float2 v11 = *(const float2*)(rp1 + 16 * ks + 2 * t + 8);
        af[ks][0] = packh2(v00.x, v00.y);
        af[ks][1] = packh2(v10.x, v10.y);
        af[ks][2] = packh2(v01.x, v01.y);
        af[ks][3] = packh2(v11.x, v11.y);
    }

    // ---- GEMM1 ----
    float acc[8][4];
#pragma unroll
    for (int nt = 0; nt < 8; nt++)
#pragma unroll
        for (int c = 0; c < 4; c++) acc[nt][c] = 0.f;

#pragma unroll
    for (int ks = 0; ks < 2; ks++)
#pragma unroll
        for (int ntp = 0; ntp < 4; ntp++) {
            uint4 bb = sB1h[(ks * 4 + ntp) * 32 + lane];
            MMA_F16(acc[2 * ntp],     af[ks], bb.x, bb.y);
            MMA_F16(acc[2 * ntp + 1], af[ks], bb.z, bb.w);
        }

    // ---- tanh(+b1) -> GEMM2 A-fragments in registers ----
    uint32_t ah[4][4];
#pragma unroll
    for (int ks = 0; ks < 4; ks++) {
        int c0 = 16 * ks + 2 * t;
        int c1 = c0 + 8;
        float b00 = sBV[c0], b01 = sBV[c0 + 1];
        float b10 = sBV[c1], b11 = sBV[c1 + 1];
        ah[ks][0] = packh2(tanh_fast(acc[2 * ks][0] + b00),
                           tanh_fast(acc[2 * ks][1] + b01));
        ah[ks][1] = packh2(tanh_fast(acc[2 * ks][2] + b00),
                           tanh_fast(acc[2 * ks][3] + b01));
        ah[ks][2] = packh2(tanh_fast(acc[2 * ks + 1][0] + b10),
                           tanh_fast(acc[2 * ks + 1][1] + b11));
        ah[ks][3] = packh2(tanh_fast(acc[2 * ks + 1][2] + b10),
                           tanh_fast(acc[2 * ks + 1][3] + b11));
    }

    // ---- GEMM2 ----
#pragma unroll
    for (int nt = 0; nt < 8; nt++)
#pragma unroll
        for (int c = 0; c < 4; c++) acc[nt][c] = 0.f;

#pragma unroll
    for (int ks = 0; ks < 4; ks++)
#pragma unroll
        for (int ntp = 0; ntp < 4; ntp++) {
            uint4 bb = sB2h[(ks * 4 + ntp) * 32 + lane];
            MMA_F16(acc[2 * ntp],     ah[ks], bb.x, bb.y);
            MMA_F16(acc[2 * ntp + 1], ah[ks], bb.z, bb.w);
        }

    // ---- +b2, pack fp16, store F ----
    uint32_t* f0 = g_f + (size_t)(rowbase + g) * 32;
    uint32_t* f1 = g_f + (size_t)(rowbase + g + 8) * 32;
#pragma unroll
    for (int nt = 0; nt < 8; nt++) {
        int c = 8 * nt + 2 * t;
        float bx = sB2V[c], by = sB2V[c + 1];
        f0[4 * nt + t] = packh2(acc[nt][0] + bx, acc[nt][1] + by);
        f1[4 * nt + t] = packh2(acc[nt][2] + bx, acc[nt][3] + by);
    }
}

// ---------------------------------------------------------------------------
// Kernel B: epilogue. One CTA per 2 atoms, 256 threads (warps 0-3 atom0,
// 4-7 atom1). Loads F fragments, gathers x, logits + online softmax,
// cross-warp merge, attn and output MLP.
// ---------------------------------------------------------------------------
__global__ __launch_bounds__(256)
void epilogue_kernel(const int*   __restrict__ nbr_list,
                     const float* __restrict__ nbrf,
                     const float* __restrict__ W3, const float* __restrict__ b3,
                     const float* __restrict__ W4, const float* __restrict__ b4,
                     float* __restrict__ out,
                     float* __restrict__ attn)
{
    __shared__ int   sNL[200];
    __shared__ float sNF[NF];
    __shared__ float sLG[200];
    __shared__ float sMG[2 * 4 * 4 * 18];
    __shared__ float sVC[128];
    __shared__ float sFN[4];
    __shared__ float sHD[128];

    const int tid  = threadIdx.x;
    const int wid  = tid >> 5;
    const int lane = tid & 31;
    const int g    = lane >> 2;
    const int t    = lane & 3;
    const int a    = wid >> 2;
    const int wt   = wid & 3;
    const int bn0  = blockIdx.x * 2;
    const int b    = bn0 / NN;

    if (tid < 200) {
        int aa = tid / 100, m = tid % 100;
        sNL[tid] = (m < MM) ? nbr_list[(bn0 + aa) * MM + m] : 0;
    }
    if (tid < NF) sNF[tid] = nbrf[tid];
    __syncthreads();

    const float*    gx_b = g_x + b * (NN * NF);
    const uint32_t* f_a  = g_f + (size_t)(bn0 + a) * MM * 32;
    const int*      nlA  = sNL + a * 100;
    float*          lgA  = sLG + a * 100;

    float m_run = -1e30f, d_run = 0.f;
    float agg[16];
#pragma unroll
    for (int i = 0; i < 16; i++) agg[i] = 0.f;

#pragma unroll
    for (int mt = 0; mt < 2; mt++) {
        const int rowbase = (wt * 2 + mt) * 16;
        int r0 = rowbase + g;
        int r1 = r0 + 8;
        bool v0 = r0 < MM, v1 = r1 < MM;
        int nb0 = v0 ? nlA[r0] : 0;
        int nb1 = v1 ? nlA[r1] : 0;
        const float*    x0p = gx_b + nb0 * NF;
        const float*    x1p = gx_b + nb1 * NF;
        const uint32_t* f0  = f_a + (size_t)(v0 ? r0 : 0) * 32;
        const uint32_t* f1  = f_a + (size_t)(v1 ? r1 : 0) * 32;

        float cf[8][4];
        float p0 = 0.f, p1 = 0.f;
#pragma unroll
        for (int nt = 0; nt < 8; nt++) {
            int c = 8 * nt + 2 * t;
            float2 fv0 = unpackh2(f0[4 * nt + t]);
            float2 fv1 = unpackh2(f1[4 * nt + t]);
            float2 x0  = *(const float2*)(x0p + c);
            float2 x1  = *(const float2*)(x1p + c);
            float2 nf  = *(const float2*)(sNF + c);
            cf[nt][0] = x0.x * fv0.x;
            cf[nt][1] = x0.y * fv0.y;
            cf[nt][2] = x1.x * fv1.x;
            cf[nt][3] = x1.y * fv1.y;
            p0 += cf[nt][0] * nf.x + cf[nt][1] * nf.y;
            p1 += cf[nt][2] * nf.x + cf[nt][3] * nf.y;
        }
        p0 += __shfl_xor_sync(0xffffffffu, p0, 1);
        p0 += __shfl_xor_sync(0xffffffffu, p0, 2);
        p1 += __shfl_xor_sync(0xffffffffu, p1, 1);
        p1 += __shfl_xor_sync(0xffffffffu, p1, 2);
        if (v0 && t == 0) lgA[r0] = p0;
        if (v1 && t == 0) lgA[r1] = p1;

        if (v0) {
            float mn = fmaxf(m_run, p0);
            float s  = __expf(m_run - mn);
            float e  = __expf(p0 - mn);
            d_run = d_run * s + e;
#pragma unroll
            for (int nt = 0; nt < 8; nt++) {
                agg[2 * nt]     = agg[2 * nt]     * s + e * cf[nt][0];
                agg[2 * nt + 1] = agg[2 * nt + 1] * s + e * cf[nt][1];
            }
            m_run = mn;
        }
        if (v1) {
            float mn = fmaxf(m_run, p1);
            float s  = __expf(m_run - mn);
            float e  = __expf(p1 - mn);
            d_run = d_run * s + e;
#pragma unroll
            for (int nt = 0; nt < 8; nt++) {
                agg[2 * nt]     = agg[2 * nt]     * s + e * cf[nt][2];
                agg[2 * nt + 1] = agg[2 * nt + 1] * s + e * cf[nt][3];
            }
            m_run = mn;
        }
    }

    // ---- in-warp butterfly merge across row groups ----
#pragma unroll
    for (int off = 4; off <= 16; off <<= 1) {
        float m2 = __shfl_xor_sync(0xffffffffu, m_run, off);
        float d2 = __shfl_xor_sync(0xffffffffu, d_run, off);
        float mn = fmaxf(m_run, m2);
        float s1 = __expf(m_run - mn);
        float s2 = __expf(m2 - mn);
        d_run = d_run * s1 + d2 * s2;
#pragma unroll
        for (int i = 0; i < 16; i++) {
            float a2 = __shfl_xor_sync(0xffffffffu, agg[i], off);
            agg[i] = agg[i] * s1 + a2 * s2;
        }
        m_run = mn;
    }

    // ---- cross-warp merge via smem ----
    if (lane < 4) {
        float* dst = sMG + (((a * 4 + wt) * 4) + lane) * 18;
        dst[0] = m_run; dst[1] = d_run;
#pragma unroll
        for (int i = 0; i < 16; i++) dst[2 + i] = agg[i];
    }
    __syncthreads();

    if (tid < 8) {
        int aa = tid >> 2, tt4 = tid & 3;
        const float* s0 = sMG + ((aa * 4 + 0) * 4 + tt4) * 18;
        float mf = s0[0], df = s0[1], ag[16];
#pragma unroll
        for (int i = 0; i < 16; i++) ag[i] = s0[2 + i];
#pragma unroll
        for (int w = 1; w < 4; w++) {
            const float* sw = sMG + ((aa * 4 + w) * 4 + tt4) * 18;
            float m2 = sw[0], d2 = sw[1];
            float mn = fmaxf(mf, m2);
            float s1 = __expf(mf - mn);
            float s2 = __expf(m2 - mn);
            df = df * s1 + d2 * s2;
#pragma unroll
            for (int i = 0; i < 16; i++) ag[i] = ag[i] * s1 + sw[2 + i] * s2;
            mf = mn;
        }
        float inv = 1.f / df;
#pragma unroll
        for (int nt = 0; nt < 8; nt++) {
            int c = 8 * nt + 2 * tt4;
            sVC[aa * 64 + c]     = ag[2 * nt] * inv;
            sVC[aa * 64 + c + 1] = ag[2 * nt + 1] * inv;
        }
        if (tt4 == 0) { sFN[2 * aa] = mf; sFN[2 * aa + 1] = df; }
    }
    __syncthreads();

    // ---- attn outputs ----
    {
        int aa  = tid >> 7;
        int ltd = tid & 127;
        if (ltd < MM)
            attn[(bn0 + aa) * MM + ltd] =
                __expf(sLG[aa * 100 + ltd] - sFN[2 * aa]) / sFN[2 * aa + 1];
    }

    // ---- output MLP, k-split across lane quads ----
    {
        const int j = tid >> 2;
        const int s = tid & 3;
        float t0 = 0.f, t1 = 0.f;
#pragma unroll
        for (int i = 0; i < 16; i++) {
            int k = 4 * i + s;
            float w = __ldg(W3 + k * NF + j);
            t0 = fmaf(sVC[k],      w, t0);
            t1 = fmaf(sVC[64 + k], w, t1);
        }
        t0 += __shfl_xor_sync(0xffffffffu, t0, 1);
        t0 += __shfl_xor_sync(0xffffffffu, t0, 2);
        t1 += __shfl_xor_sync(0xffffffffu, t1, 1);
        t1 += __shfl_xor_sync(0xffffffffu, t1, 2);
        if (s == 0) {
            float bj = __ldg(b3 + j);
            sHD[j]      = tanh_fast(t0 + bj);
            sHD[64 + j] = tanh_fast(t1 + bj);
        }
    }
    __syncthreads();
    {
        const int j = tid >> 2;
        const int s = tid & 3;
        float o0 = 0.f, o1 = 0.f;
#pragma unroll
        for (int i = 0; i < 16; i++) {
            int k = 4 * i + s;
            float w = __ldg(W4 + k * NF + j);
            o0 = fmaf(sHD[k],      w, o0);
            o1 = fmaf(sHD[64 + k], w, o1);
        }
        o0 += __shfl_xor_sync(0xffffffffu, o0, 1);
        o0 += __shfl_xor_sync(0xffffffffu, o0, 2);
        o1 += __shfl_xor_sync(0xffffffffu, o1, 1);
        o1 += __shfl_xor_sync(0xffffffffu, o1, 2);
        if (s == 0) {
            float bj = __ldg(b4 + j);
            out[bn0 * NF + j]       = o0 + bj;
            out[(bn0 + 1) * NF + j] = o1 + bj;
        }
    }
}

// ---------------------------------------------------------------------------
extern "C" void kernel_launch(void* const* d_in, const int* in_sizes, int n_in,
                              void* d_out, int out_size)
{
    const float* features = (const float*)d_in[0];
    const float* rbf      = (const float*)d_in[1];
    const int*   nbr      = (const int*)  d_in[2];
    const float* W0       = (const float*)d_in[3];
    const float* W1       = (const float*)d_in[4];
    const float* b1       = (const float*)d_in[5];
    const float* W2       = (const float*)d_in[6];
    const float* b2       = (const float*)d_in[7];
    const float* nbrf     = (const float*)d_in[8];
    const float* W3       = (const float*)d_in[9];
    const float* b3       = (const float*)d_in[10];
    const float* W4       = (const float*)d_in[11];
    const float* b4       = (const float*)d_in[12];

    float* out  = (float*)d_out;                 // [B, N, NF]
    float* attn = out + BB * NN * NF;            // [B, N, M]

    const int setup_elems = SETUP_W + BB * NN * NF;
    setup_kernel<<<(setup_elems + 255) / 256, 256>>>(W1, W2, features, W0);
    gemm_kernel<<<NROWS / 128, 256>>>(rbf, b1, b2);
    epilogue_kernel<<<BB * NN / 2, 256>>>(nbr, nbrf, W3, b3, W4, b4, out, attn);
}

// round 15
// speedup vs baseline: 1.3726x; 1.3726x over previous
#include <cuda_runtime.h>
#include <cuda_fp16.h>
#include <math.h>
#include <cstdint>

#define BB  64
#define NN  100
#define MM  99
#define NIN 32
#define NG  32
#define NF  64

// ---------------- smem layout (bytes) --------------------------------------
#define U_STR32  36                      // uint32 (half2) stride per row
#define UW_BYTES 2304
#define B1H_OFF  18432                   // W1 frags: [2 ks][4 ntp][32] uint4 = 4 KB
#define B2H_OFF  22528                   // W2 frags: [4 ks][4 ntp][32] uint4 = 8 KB
#define SNL_OFF  30720                   // [2][100] int
#define SBV_OFF  31520                   // b1 [64]
#define SB2V_OFF 31776                   // b2 [64]
#define SNF_OFF  32032                   // nbrf [64]
#define SLG_OFF  32288                   // [2][100]
#define SMG_OFF  33088                   // [2][4][4][18] f32
#define SVC_OFF  35392                   // [2][64]
#define SFN_OFF  35904                   // [2][2]
#define SHD_OFF  35920                   // [2][64]
#define SMEM_TOTAL 36448

static __device__ __forceinline__ float tanh_fast(float x) {
    float y; asm("tanh.approx.f32 %0, %1;" : "=f"(y) : "f"(x)); return y;
}
static __device__ __forceinline__ uint32_t packh2(float a, float b) {
    __half2 h = __floats2half2_rn(a, b);
    return *reinterpret_cast<uint32_t*>(&h);
}
static __device__ __forceinline__ uint32_t tanh_h2(uint32_t x) {
    uint32_t y; asm("tanh.approx.f16x2 %0, %1;" : "=r"(y) : "r"(x)); return y;
}
static __device__ __forceinline__ uint32_t hadd2(uint32_t a, uint32_t b) {
    uint32_t y; asm("add.rn.f16x2 %0, %1, %2;" : "=r"(y) : "r"(a), "r"(b)); return y;
}

#define MMA_F16(c, a, b0, b1v)                                                     \
    asm volatile("mma.sync.aligned.m16n8k16.row.col.f32.f16.f16.f32 "              \
        "{%0,%1,%2,%3},{%4,%5,%6,%7},{%8,%9},{%0,%1,%2,%3};"                       \
        : "+f"((c)[0]), "+f"((c)[1]), "+f"((c)[2]), "+f"((c)[3])                   \
        : "r"((a)[0]), "r"((a)[1]), "r"((a)[2]), "r"((a)[3]), "r"(b0), "r"(b1v))

__device__ float g_x[BB * NN * NF];          // x = features @ W0 (f32)
__device__ uint4 g_w1h[2 * 4 * 32];          // W1 fp16 fragment-major
__device__ uint4 g_w2h[4 * 4 * 32];          // W2 fp16 fragment-major

// ---------------------------------------------------------------------------
// Fused setup: fp16 fragment weight prep + x = features @ W0
// ---------------------------------------------------------------------------
#define W1H_N   256
#define W2H_N   512
#define SETUP_W (W1H_N + W2H_N)           // 768
__global__ void setup_kernel(const float* __restrict__ W1,
                             const float* __restrict__ W2,
                             const float* __restrict__ features,
                             const float* __restrict__ W0)
{
    int idx = blockIdx.x * blockDim.x + threadIdx.x;
    if (idx < SETUP_W) {
        const float* W = (idx < W1H_N) ? W1 : W2;
        int e = (idx < W1H_N) ? idx : idx - W1H_N;
        int lane = e & 31, blk = e >> 5;
        int ks = blk >> 2, ntp = blk & 3;
        int g = lane >> 2, t = lane & 3;
        int kb = ks * 16;
        int n0 = (2 * ntp) * 8 + g;
        int n1 = (2 * ntp + 1) * 8 + g;
        uint4 v;
        v.x = packh2(W[(kb + 2 * t) * NF + n0],     W[(kb + 2 * t + 1) * NF + n0]);
        v.y = packh2(W[(kb + 2 * t + 8) * NF + n0], W[(kb + 2 * t + 9) * NF + n0]);
        v.z = packh2(W[(kb + 2 * t) * NF + n1],     W[(kb + 2 * t + 1) * NF + n1]);
        v.w = packh2(W[(kb + 2 * t + 8) * NF + n1], W[(kb + 2 * t + 9) * NF + n1]);
        if (idx < W1H_N) g_w1h[e] = v; else g_w2h[e] = v;
        return;
    }
    int ix = idx - SETUP_W;
    if (ix >= BB * NN * NF) return;
    int f   = ix & (NF - 1);
    int row = ix >> 6;
    const float* feat = features + row * NIN;
    float acc = 0.f;
#pragma unroll
    for (int k = 0; k < NIN; k++)
        acc = fmaf(feat[k], W0[k * NF + f], acc);
    g_x[ix] = acc;
}

// ---------------------------------------------------------------------------
// One CTA per 2 atoms. 256 threads: warps 0-3 atom0, 4-7 atom1.
// Warp-local 16-row chunks. tanh in f16x2 feeds GEMM2 A-regs directly;
// chunk-1 rbf prefetched into registers during chunk 0; b2 folded into
// GEMM2 accumulator init.
// ---------------------------------------------------------------------------
__global__ __launch_bounds__(256, 3)
void interaction_kernel(const float* __restrict__ rbf,
                        const int*   __restrict__ nbr_list,
                        const float* __restrict__ b1,
                        const float* __restrict__ b2,
                        const float* __restrict__ nbrf,
                        const float* __restrict__ W3, const float* __restrict__ b3,
                        const float* __restrict__ W4, const float* __restrict__ b4,
                        float* __restrict__ out,
                        float* __restrict__ attn)
{
    extern __shared__ __align__(16) char smem[];
    uint4*  sB1h = (uint4*)(smem + B1H_OFF);
    uint4*  sB2h = (uint4*)(smem + B2H_OFF);
    int*    sNL  = (int*)  (smem + SNL_OFF);
    float*  sBV  = (float*)(smem + SBV_OFF);
    float*  sB2V = (float*)(smem + SB2V_OFF);
    float*  sNF  = (float*)(smem + SNF_OFF);
    float*  sLG  = (float*)(smem + SLG_OFF);
    float*  sMG  = (float*)(smem + SMG_OFF);
    float*  sVC  = (float*)(smem + SVC_OFF);
    float*  sFN  = (float*)(smem + SFN_OFF);
    float*  sHD  = (float*)(smem + SHD_OFF);

    const int tid  = threadIdx.x;
    const int wid  = tid >> 5;
    const int lane = tid & 31;
    const int g    = lane >> 2;
    const int t    = lane & 3;
    const int a    = wid >> 2;            // atom within CTA
    const int wt   = wid & 3;             // warp within atom group
    const int bn0  = blockIdx.x * 2;
    const int b    = bn0 / NN;

    // ---- cooperative stage (one barrier) ----
    for (int idx = tid; idx < W1H_N; idx += 256) sB1h[idx] = g_w1h[idx];
    for (int idx = tid; idx < W2H_N; idx += 256) sB2h[idx] = g_w2h[idx];
    if (tid < 200) {
        int aa = tid / 100, m = tid % 100;
        sNL[tid] = (m < MM) ? nbr_list[(bn0 + aa) * MM + m] : 0;
    }
    if (tid < NF) {
        sBV[tid]  = b1[tid];
        sB2V[tid] = b2[tid];
        sNF[tid]  = nbrf[tid];
    }
    __syncthreads();

    // packed b1 biases for the f16x2 tanh path (8 regs, constant per thread)
    uint32_t bh[8];
#pragma unroll
    for (int ks = 0; ks < 4; ks++) {
        int c0 = 16 * ks + 2 * t;
        int c1 = c0 + 8;
        bh[2 * ks]     = packh2(sBV[c0], sBV[c0 + 1]);
        bh[2 * ks + 1] = packh2(sBV[c1], sBV[c1 + 1]);
    }

    uint32_t* sU = (uint32_t*)(smem + wid * UW_BYTES);   // [16 rows][36 u32]
    const float* rbf_a = rbf + (size_t)(bn0 + a) * MM * NG;
    const float* gx_b  = g_x + b * (NN * NF);
    const int*   nlA   = sNL + a * 100;
    float*       lgA   = sLG + a * 100;

    // ---- stage chunk 0 into slab; prefetch chunk 1 into regs ----
    const int sr = lane >> 3;             // unused rows pattern helper
    (void)sr;
    uint2 pf[2];
    {
        // chunk 0 rows = [wt*32, wt*32+16)
#pragma unroll
        for (int q = 0; q < 4; q++) {
            int idx = q * 32 + lane;
            int r   = idx >> 3;
            int c4  = idx & 7;
            int grow = wt * 32 + r;
            uint2 hv = make_uint2(0u, 0u);
            if (grow < MM) {
                float4 v = *(const float4*)(rbf_a + (size_t)grow * NG + 4 * c4);
                hv.x = packh2(v.x, v.y);
                hv.y = packh2(v.z, v.w);
            }
            *(uint2*)(sU + r * U_STR32 + 2 * c4) = hv;
        }
        // chunk 1 rows = [wt*32+16, wt*32+32): prefetch 2 uint2 per thread? 4 per thread
    }
    uint2 pf2[2];
#pragma unroll
    for (int q = 0; q < 4; q++) {
        int idx = q * 32 + lane;
        int r   = idx >> 3;
        int c4  = idx & 7;
        int grow = wt * 32 + 16 + r;
        uint2 hv = make_uint2(0u, 0u);
        if (grow < MM) {
            float4 v = *(const float4*)(rbf_a + (size_t)grow * NG + 4 * c4);
            hv.x = packh2(v.x, v.y);
            hv.y = packh2(v.z, v.w);
        }
        if (q < 2) pf[q] = hv; else pf2[q - 2] = hv;
    }
    __syncwarp();

    float m_run = -1e30f, d_run = 0.f;
    float agg[16];
#pragma unroll
    for (int i = 0; i < 16; i++) agg[i] = 0.f;

#pragma unroll
    for (int mt = 0; mt < 2; mt++) {
        const int rowbase = wt * 32 + mt * 16;

        // ---- GEMM1: D1[16,64] = A[16,32] @ W1, 2 k16 steps ----
        float acc[8][4];
#pragma unroll
        for (int nt = 0; nt < 8; nt++)
#pragma unroll
            for (int c = 0; c < 4; c++) acc[nt][c] = 0.f;

#pragma unroll
        for (int ks = 0; ks < 2; ks++) {
            uint32_t af[4];
            af[0] = sU[g * U_STR32 + ks * 8 + t];
            af[1] = sU[(g + 8) * U_STR32 + ks * 8 + t];
            af[2] = sU[g * U_STR32 + ks * 8 + t + 4];
            af[3] = sU[(g + 8) * U_STR32 + ks * 8 + t + 4];
#pragma unroll
            for (int ntp = 0; ntp < 4; ntp++) {
                uint4 bb = sB1h[(ks * 4 + ntp) * 32 + lane];
                MMA_F16(acc[2 * ntp],     af, bb.x, bb.y);
                MMA_F16(acc[2 * ntp + 1], af, bb.z, bb.w);
            }
        }
        __syncwarp();

        // ---- restage slab with prefetched chunk-1 rows (overlaps compute) ----
        if (mt == 0) {
#pragma unroll
            for (int q = 0; q < 4; q++) {
                int idx = q * 32 + lane;
                int r   = idx >> 3;
                int c4  = idx & 7;
                *(uint2*)(sU + r * U_STR32 + 2 * c4) = (q < 2) ? pf[q] : pf2[q - 2];
            }
        }

        // ---- tanh(+b1) in f16x2 -> GEMM2 A-fragments ----
        uint32_t ah[4][4];
#pragma unroll
        for (int ks = 0; ks < 4; ks++) {
            ah[ks][0] = tanh_h2(hadd2(packh2(acc[2 * ks][0],     acc[2 * ks][1]),     bh[2 * ks]));
            ah[ks][1] = tanh_h2(hadd2(packh2(acc[2 * ks][2],     acc[2 * ks][3]),     bh[2 * ks]));
            ah[ks][2] = tanh_h2(hadd2(packh2(acc[2 * ks + 1][0], acc[2 * ks + 1][1]), bh[2 * ks + 1]));
            ah[ks][3] = tanh_h2(hadd2(packh2(acc[2 * ks + 1][2], acc[2 * ks + 1][3]), bh[2 * ks + 1]));
        }

        // ---- GEMM2: acc init = b2 (folds the epilogue +b2) ----
#pragma unroll
        for (int nt = 0; nt < 8; nt++) {
            float2 bb = *(const float2*)(sB2V + 8 * nt + 2 * t);
            acc[nt][0] = bb.x; acc[nt][1] = bb.y;
            acc[nt][2] = bb.x; acc[nt][3] = bb.y;
        }

#pragma unroll
        for (int ks = 0; ks < 4; ks++) {
#pragma unroll
            for (int ntp = 0; ntp < 4; ntp++) {
                uint4 bb = sB2h[(ks * 4 + ntp) * 32 + lane];
                MMA_F16(acc[2 * ntp],     ah[ks], bb.x, bb.y);
                MMA_F16(acc[2 * ntp + 1], ah[ks], bb.z, bb.w);
            }
        }

        // ---- epilogue for this chunk's 2 rows per lane ----
        {
            int r0 = rowbase + g;
            int r1 = r0 + 8;
            bool v0 = r0 < MM, v1 = r1 < MM;
            int nb0 = v0 ? nlA[r0] : 0;
            int nb1 = v1 ? nlA[r1] : 0;
            const float* x0p = gx_b + nb0 * NF;
            const float* x1p = gx_b + nb1 * NF;
            float p0 = 0.f, p1 = 0.f;
#pragma unroll
            for (int nt = 0; nt < 8; nt++) {
                int c = 8 * nt + 2 * t;
                float2 x0 = *(const float2*)(x0p + c);
                float2 x1 = *(const float2*)(x1p + c);
                float2 nf = *(const float2*)(sNF + c);
                float cf00 = x0.x * acc[nt][0];
                float cf01 = x0.y * acc[nt][1];
                float cf10 = x1.x * acc[nt][2];
                float cf11 = x1.y * acc[nt][3];
                acc[nt][0] = cf00; acc[nt][1] = cf01;
                acc[nt][2] = cf10; acc[nt][3] = cf11;
                p0 += cf00 * nf.x + cf01 * nf.y;
                p1 += cf10 * nf.x + cf11 * nf.y;
            }
            p0 += __shfl_xor_sync(0xffffffffu, p0, 1);
            p0 += __shfl_xor_sync(0xffffffffu, p0, 2);
            p1 += __shfl_xor_sync(0xffffffffu, p1, 1);
            p1 += __shfl_xor_sync(0xffffffffu, p1, 2);
            if (v0 && t == 0) lgA[r0] = p0;
            if (v1 && t == 0) lgA[r1] = p1;

            if (v0) {
                float mn = fmaxf(m_run, p0);
                float s  = __expf(m_run - mn);
                float e  = __expf(p0 - mn);
                d_run = d_run * s + e;
#pragma unroll
                for (int nt = 0; nt < 8; nt++) {
                    agg[2 * nt]     = agg[2 * nt]     * s + e * acc[nt][0];
                    agg[2 * nt + 1] = agg[2 * nt + 1] * s + e * acc[nt][1];
                }
                m_run = mn;
            }
            if (v1) {
                float mn = fmaxf(m_run, p1);
                float s  = __expf(m_run - mn);
                float e  = __expf(p1 - mn);
                d_run = d_run * s + e;
#pragma unroll
                for (int nt = 0; nt < 8; nt++) {
                    agg[2 * nt]     = agg[2 * nt]     * s + e * acc[nt][2];
                    agg[2 * nt + 1] = agg[2 * nt + 1] * s + e * acc[nt][3];
                }
                m_run = mn;
            }
        }
        __syncwarp();   // chunk-1 slab stores visible before its GEMM1 reads
    }

    // ---- in-warp butterfly merge across row groups ----
#pragma unroll
    for (int off = 4; off <= 16; off <<= 1) {
        float m2 = __shfl_xor_sync(0xffffffffu, m_run, off);
        float d2 = __shfl_xor_sync(0xffffffffu, d_run, off);
        float mn = fmaxf(m_run, m2);
        float s1 = __expf(m_run - mn);
        float s2 = __expf(m2 - mn);
        d_run = d_run * s1 + d2 * s2;
#pragma unroll
        for (int i = 0; i < 16; i++) {
            float a2 = __shfl_xor_sync(0xffffffffu, agg[i], off);
            agg[i] = agg[i] * s1 + a2 * s2;
        }
        m_run = mn;
    }

    // ---- cross-warp merge via smem ----
    if (lane < 4) {
        float* dst = sMG + (((a * 4 + wt) * 4) + lane) * 18;
        dst[0] = m_run; dst[1] = d_run;
#pragma unroll
        for (int i = 0; i < 16; i++) dst[2 + i] = agg[i];
    }
    __syncthreads();

    if (tid < 8) {
        int aa = tid >> 2, tt4 = tid & 3;
        const float* s0 = sMG + ((aa * 4 + 0) * 4 + tt4) * 18;
        float mf = s0[0], df = s0[1], ag[16];
#pragma unroll
        for (int i = 0; i < 16; i++) ag[i] = s0[2 + i];
#pragma unroll
        for (int w = 1; w < 4; w++) {
            const float* sw = sMG + ((aa * 4 + w) * 4 + tt4) * 18;
            float m2 = sw[0], d2 = sw[1];
            float mn = fmaxf(mf, m2);
            float s1 = __expf(mf - mn);
            float s2 = __expf(m2 - mn);
            df = df * s1 + d2 * s2;
#pragma unroll
            for (int i = 0; i < 16; i++) ag[i] = ag[i] * s1 + sw[2 + i] * s2;
            mf = mn;
        }
        float inv = 1.f / df;
#pragma unroll
        for (int nt = 0; nt < 8; nt++) {
            int c = 8 * nt + 2 * tt4;
            sVC[aa * 64 + c]     = ag[2 * nt] * inv;
            sVC[aa * 64 + c + 1] = ag[2 * nt + 1] * inv;
        }
        if (tt4 == 0) { sFN[2 * aa] = mf; sFN[2 * aa + 1] = df; }
    }
    __syncthreads();

    // ---- attn outputs ----
    {
        int aa  = tid >> 7;
        int ltd = tid & 127;
        if (ltd < MM)
            attn[(bn0 + aa) * MM + ltd] =
                __expf(sLG[aa * 100 + ltd] - sFN[2 * aa]) / sFN[2 * aa + 1];
    }

    // ---- output MLP, k-split across lane quads ----
    {
        const int j = tid >> 2;
        const int s = tid & 3;
        float t0 = 0.f, t1 = 0.f;
#pragma unroll
        for (int i = 0; i < 16; i++) {
            int k = 4 * i + s;
            float w = __ldg(W3 + k * NF + j);
            t0 = fmaf(sVC[k],      w, t0);
            t1 = fmaf(sVC[64 + k], w, t1);
        }
        t0 += __shfl_xor_sync(0xffffffffu, t0, 1);
        t0 += __shfl_xor_sync(0xffffffffu, t0, 2);
        t1 += __shfl_xor_sync(0xffffffffu, t1, 1);
        t1 += __shfl_xor_sync(0xffffffffu, t1, 2);
        if (s == 0) {
            float bj = __ldg(b3 + j);
            sHD[j]      = tanh_fast(t0 + bj);
            sHD[64 + j] = tanh_fast(t1 + bj);
        }
    }
    __syncthreads();
    {
        const int j = tid >> 2;
        const int s = tid & 3;
        float o0 = 0.f, o1 = 0.f;
#pragma unroll
        for (int i = 0; i < 16; i++) {
            int k = 4 * i + s;
            float w = __ldg(W4 + k * NF + j);
            o0 = fmaf(sHD[k],      w, o0);
            o1 = fmaf(sHD[64 + k], w, o1);
        }
        o0 += __shfl_xor_sync(0xffffffffu, o0, 1);
        o0 += __shfl_xor_sync(0xffffffffu, o0, 2);
        o1 += __shfl_xor_sync(0xffffffffu, o1, 1);
        o1 += __shfl_xor_sync(0xffffffffu, o1, 2);
        if (s == 0) {
            float bj = __ldg(b4 + j);
            out[bn0 * NF + j]       = o0 + bj;
            out[(bn0 + 1) * NF + j] = o1 + bj;
        }
    }
}

// ---------------------------------------------------------------------------
extern "C" void kernel_launch(void* const* d_in, const int* in_sizes, int n_in,
                              void* d_out, int out_size)
{
    const float* features = (const float*)d_in[0];
    const float* rbf      = (const float*)d_in[1];
    const int*   nbr      = (const int*)  d_in[2];
    const float* W0       = (const float*)d_in[3];
    const float* W1       = (const float*)d_in[4];
    const float* b1       = (const float*)d_in[5];
    const float* W2       = (const float*)d_in[6];
    const float* b2       = (const float*)d_in[7];
    const float* nbrf     = (const float*)d_in[8];
    const float* W3       = (const float*)d_in[9];
    const float* b3       = (const float*)d_in[10];
    const float* W4       = (const float*)d_in[11];
    const float* b4       = (const float*)d_in[12];

    float* out  = (float*)d_out;                 // [B, N, NF]
    float* attn = out + BB * NN * NF;            // [B, N, M]

    cudaFuncSetAttribute(interaction_kernel,
                         cudaFuncAttributeMaxDynamicSharedMemorySize, SMEM_TOTAL);

    const int setup_elems = SETUP_W + BB * NN * NF;
    setup_kernel<<<(setup_elems + 255) / 256, 256>>>(W1, W2, features, W0);
    interaction_kernel<<<BB * NN / 2, 256, SMEM_TOTAL>>>(rbf, nbr, b1, b2, nbrf,
                                                         W3, b3, W4, b4, out, attn);
}